// round 12
// baseline (speedup 1.0000x reference)
#include <cuda_runtime.h>
#include <cuda_bf16.h>

// Jones 4-pol congruence: V_p[a,d,n,t,f] = sum_{b,c} J[a,b,ant1[n],t,f] *
//                         V_m[b,c,n,t,f] * J[d,c,ant2[n],t,f]
// Layouts (row-major): V_m (2,2,NBL,T,F), jones (2,2,NANT,T,F), out (2,2,NBL,T,F)
//
// History: R4 best (155.5us): 12 front-batched loads, .cs loads+stores, 64 regs.
// R5/R6 (depth) and R8 (store policy) all FAILED -> kernel is LTS-bound:
// L2-side traffic ~2.1GB (Vm 528 + stores 528 + Jones 1056 MB) runs at the
// ~6300 B/cyc LTS practical cap. Jones is half the LTS traffic and has zero
// L1 reuse because antenna-sharing baselines are scattered.
// R9: counting-sort baselines by ant1 (tiny setup kernel -> __device__ perm);
// main kernel: CTA = 8 warps = 8 baselines sharing ant1, same 128-elem
// tf-chunk -> ant1-Jones lines L1-hit for 7/8 warps -> LTS traffic -21%.

#define NPOL   2
#define NANT   64
#define NBL    2016
#define NTIMES 64
#define NFREQS 256

#define TF      (NTIMES * NFREQS)   // 16384
#define SPLANE  (NBL * TF)          // 33,030,144  (V_m / out plane stride)
#define SJPLANE (NANT * TF)         // 1,048,576   (jones plane stride)

#define BL_PER_CTA 8                // one baseline per warp
#define NGROUPC    (NBL / BL_PER_CTA)   // 252 baseline-groups
#define CHUNK_E    128              // tf elems per warp-chunk (32 lanes x 4)
#define NCHUNKS    (TF / CHUNK_E)   // 128
#define NCTAS      (NGROUPC * NCHUNKS)  // 32256

__device__ int d_perm[NBL];

// --- setup: counting sort of baselines by ant1 (1 CTA, 64 threads) ---
__global__ void sort_baselines_kernel(const int* __restrict__ ant1)
{
    __shared__ int cnt[NANT];
    __shared__ int off[NANT];
    int a = threadIdx.x;            // this thread owns antenna value a

    int c = 0;
    for (int i = 0; i < NBL; i++)   // broadcast loads (all lanes same addr)
        c += (__ldg(&ant1[i]) == a);
    cnt[a] = c;
    __syncthreads();

    if (a == 0) {
        int s = 0;
        for (int j = 0; j < NANT; j++) { off[j] = s; s += cnt[j]; }
    }
    __syncthreads();

    int pos = off[a];
    for (int i = 0; i < NBL; i++)
        if (__ldg(&ant1[i]) == a) d_perm[pos++] = i;
}

__device__ __forceinline__ float4 ldcs4(const float* p) {
    return __ldcs((const float4*)p);
}
__device__ __forceinline__ float4 ldg4(const float* p) {
    return __ldg((const float4*)p);
}
__device__ __forceinline__ void stcs4(float* p, float4 v) {
    __stcs((float4*)p, v);
}

__global__ __launch_bounds__(256, 4) void jones_congruence_kernel(
    const float* __restrict__ Vm,
    const float* __restrict__ J,
    const int*   __restrict__ ant1,
    const int*   __restrict__ ant2,
    float*       __restrict__ out)
{
    const int w    = threadIdx.x >> 5;    // warp -> baseline within group
    const int lane = threadIdx.x & 31;

    // group fast, chunk slow: concurrent wave covers many ant1-groups at the
    // same tf window (keeps the hot Jones slice small in L2 as well)
    const int group = blockIdx.x % NGROUPC;
    const int chunk = blockIdx.x / NGROUPC;

    const int n  = d_perm[group * BL_PER_CTA + w];   // baseline (ant1-sorted)
    const int tf = chunk * CHUNK_E + lane * 4;

    const int base = n * TF + tf;
    const int a1   = __ldg(&ant1[n]);
    const int a2   = __ldg(&ant2[n]);
    const int jb1  = a1 * TF + tf;       // shared across warps of this CTA -> L1 hits
    const int jb2  = a2 * TF + tf;

    // ---- front-batch ALL 12 loads (deep MLP, proven in R4) ----
    // V_m planes (stream-once: evict-first)
    float4 v00 = ldcs4(Vm + 0 * SPLANE + base);
    float4 v01 = ldcs4(Vm + 1 * SPLANE + base);
    float4 v10 = ldcs4(Vm + 2 * SPLANE + base);
    float4 v11 = ldcs4(Vm + 3 * SPLANE + base);

    // j1 = jones[:, :, ant1[n]]  (same lines for all 8 warps -> L1 reuse)
    float4 a00 = ldg4(J + 0 * SJPLANE + jb1);
    float4 a01 = ldg4(J + 1 * SJPLANE + jb1);
    float4 a10 = ldg4(J + 2 * SJPLANE + jb1);
    float4 a11 = ldg4(J + 3 * SJPLANE + jb1);

    // j2 = jones[:, :, ant2[n]]  (L2-resident)
    float4 b00 = ldg4(J + 0 * SJPLANE + jb2);
    float4 b01 = ldg4(J + 1 * SJPLANE + jb2);
    float4 b10 = ldg4(J + 2 * SJPLANE + jb2);
    float4 b11 = ldg4(J + 3 * SJPLANE + jb2);

    float4 o00, o01, o10, o11;

    // M = J1 @ V ; O[a][d] = sum_c M[a][c] * J2[d][c]  (real -> conj = id)
#define JONES_LANE(s)                                                   \
    {                                                                   \
        float m00 = a00.s * v00.s + a01.s * v10.s;                      \
        float m01 = a00.s * v01.s + a01.s * v11.s;                      \
        float m10 = a10.s * v00.s + a11.s * v10.s;                      \
        float m11 = a10.s * v01.s + a11.s * v11.s;                      \
        o00.s = m00 * b00.s + m01 * b01.s;                              \
        o01.s = m00 * b10.s + m01 * b11.s;                              \
        o10.s = m10 * b00.s + m11 * b01.s;                              \
        o11.s = m10 * b10.s + m11 * b11.s;                              \
    }

    JONES_LANE(x)
    JONES_LANE(y)
    JONES_LANE(z)
    JONES_LANE(w)
#undef JONES_LANE

    // out planes (write-once: streaming stores; proven best in R4 vs R8)
    stcs4(out + 0 * SPLANE + base, o00);
    stcs4(out + 1 * SPLANE + base, o01);
    stcs4(out + 2 * SPLANE + base, o10);
    stcs4(out + 3 * SPLANE + base, o11);
}

extern "C" void kernel_launch(void* const* d_in, const int* in_sizes, int n_in,
                              void* d_out, int out_size)
{
    const float* Vm   = (const float*)d_in[0];
    const float* J    = (const float*)d_in[1];
    const int*   ant1 = (const int*)d_in[2];
    const int*   ant2 = (const int*)d_in[3];
    float*       out  = (float*)d_out;

    sort_baselines_kernel<<<1, NANT>>>(ant1);
    jones_congruence_kernel<<<NCTAS, 256>>>(Vm, J, ant1, ant2, out);
}